// round 15
// baseline (speedup 1.0000x reference)
#include <cuda_runtime.h>
#include <cstdint>
#include <cstddef>

// ---------------------------------------------------------------------------
// GAT, N=6144, F_in=256, F_hid=64, F_out=32, H=4, dense adj.
// attn_ij = w_ij / sum_j w_ij with
//   w_ij = mask_ij * ( s2_j >= -s1_i ?  e^{s2_j} * e^{0.8 s1_i}  :  e^{0.2 s2_j} )
// Masked attention via warp-level bf16 HMMA m16n8k16 (half the HMMAs and
// half the B-fragment LDS of the tf32 m16n8k8 version). R13's proven shape:
// 256 threads, M_warp=16, i-block 128. Denominator exact fp32.
// ---------------------------------------------------------------------------

typedef uint32_t u32;

constexpr int N_  = 6144;
constexpr int NH_ = 4;
constexpr int F1_ = 64;
constexpr int F2_ = 32;
constexpr int MW_ = N_ / 32;   // 192 mask words per row
constexpr int JS1_ = 3;        // j-splits, layer 1 -> 576 CTAs
constexpr int JS2_ = 12;       // j-splits, layer 2 -> 576 CTAs

struct Scratch {
    u32 mask[(size_t)N_ * MW_];
    float H1[(size_t)NH_ * N_ * F1_];
    float P1n[(size_t)JS1_ * NH_ * N_ * F1_];
    float P1d[(size_t)JS1_ * NH_ * N_];
    float x2[(size_t)N_ * F1_];
    float H2[(size_t)N_ * F2_];
    float P2n[(size_t)JS2_ * N_ * F2_];
    float P2d[(size_t)JS2_ * N_];
    float T1[NH_ * N_], R1[NH_ * N_], S21[NH_ * N_], E2p1[NH_ * N_], E2n1[NH_ * N_];
    float T2[N_], R2[N_], S22[N_], E2p2[N_], E2n2[N_];
};
__device__ Scratch g_s;

// ---------------- helpers ---------------------------------------------------
__device__ __forceinline__ u32 packbf(float hi, float lo) {
    u32 r;
    asm("cvt.rn.bf16x2.f32 %0, %1, %2;" : "=r"(r) : "f"(hi), "f"(lo));
    return r;
}
__device__ __forceinline__ void mma_bf16(float* c,
                                         u32 a0, u32 a1, u32 a2, u32 a3,
                                         u32 b0, u32 b1) {
    asm volatile(
        "mma.sync.aligned.m16n8k16.row.col.f32.bf16.bf16.f32 "
        "{%0,%1,%2,%3}, {%4,%5,%6,%7}, {%8,%9}, {%0,%1,%2,%3};"
        : "+f"(c[0]), "+f"(c[1]), "+f"(c[2]), "+f"(c[3])
        : "r"(a0), "r"(a1), "r"(a2), "r"(a3), "r"(b0), "r"(b1));
}

// ---------------- adj -> bitmask -------------------------------------------
__global__ void pack_kernel(const int* __restrict__ adj, u32* __restrict__ mb) {
    size_t gid = (size_t)blockIdx.x * blockDim.x + threadIdx.x;
    int v = adj[gid] > 0;
    u32 m = __ballot_sync(0xffffffffu, v);
    if ((threadIdx.x & 31) == 0) mb[gid >> 5] = m;
}

// ---------------- small fp32 GEMM: C[h] = A @ B[h], 8x4 per-thread ---------
template <int F>
__global__ void gemm_kernel(const float* __restrict__ A, const float* __restrict__ B,
                            float* __restrict__ C, int K) {
    constexpr int TX = F / 4;
    constexpr int TY = 256 / TX;
    constexpr int RM = TY * 8;
    constexpr int TK = 16;
    __shared__ float xs[RM][TK + 1];
    __shared__ float ws[TK][F + 4];
    const int h  = blockIdx.y;
    const int i0 = blockIdx.x * RM;
    const float* Bh = B + (size_t)h * K * F;
    float*       Ch = C + (size_t)h * N_ * F;
    const int tid = threadIdx.x;
    const int tx = tid % TX, ty = tid / TX;
    float acc[8][4] = {};
    for (int k0 = 0; k0 < K; k0 += TK) {
        for (int idx = tid; idx < RM * TK; idx += 256) {
            int r = idx / TK, c = idx % TK;
            xs[r][c] = A[(size_t)(i0 + r) * K + k0 + c];
        }
        for (int idx = tid; idx < TK * F; idx += 256) {
            int r = idx / F, c = idx % F;
            ws[r][c] = Bh[(size_t)(k0 + r) * F + c];
        }
        __syncthreads();
#pragma unroll
        for (int kk = 0; kk < TK; kk++) {
            float a[8], b[4];
#pragma unroll
            for (int r = 0; r < 8; r++) a[r] = xs[ty * 8 + r][kk];
#pragma unroll
            for (int c = 0; c < 4; c++) b[c] = ws[kk][tx * 4 + c];
#pragma unroll
            for (int r = 0; r < 8; r++)
#pragma unroll
                for (int c = 0; c < 4; c++)
                    acc[r][c] = fmaf(a[r], b[c], acc[r][c]);
        }
        __syncthreads();
    }
#pragma unroll
    for (int r = 0; r < 8; r++)
#pragma unroll
        for (int c = 0; c < 4; c++)
            Ch[(size_t)(i0 + ty * 8 + r) * F + tx * 4 + c] = acc[r][c];
}

// ---------------- per-node scores + precomputed exponentials ---------------
template <int F>
__global__ void scores_kernel(const float* __restrict__ H, const float* __restrict__ a,
                              float* __restrict__ T, float* __restrict__ R,
                              float* __restrict__ S2, float* __restrict__ E2p,
                              float* __restrict__ E2n, int NH) {
    int gw   = (int)((blockIdx.x * blockDim.x + threadIdx.x) >> 5);
    int lane = threadIdx.x & 31;
    if (gw >= NH * N_) return;
    int h = gw / N_, i = gw % N_;
    const float* Hi = H + ((size_t)h * N_ + i) * F;
    const float* a1 = a + (size_t)h * 2 * F;
    const float* a2 = a1 + F;
    float s1 = 0.f, s2 = 0.f;
    for (int f = lane; f < F; f += 32) {
        float hv = Hi[f];
        s1 = fmaf(hv, a1[f], s1);
        s2 = fmaf(hv, a2[f], s2);
    }
#pragma unroll
    for (int o = 16; o; o >>= 1) {
        s1 += __shfl_xor_sync(0xffffffffu, s1, o);
        s2 += __shfl_xor_sync(0xffffffffu, s2, o);
    }
    if (lane == 0) {
        int idx = h * N_ + i;
        T[idx]   = -s1;
        R[idx]   = expf(0.8f * s1);
        S2[idx]  = s2;
        E2p[idx] = expf(s2);
        E2n[idx] = expf(0.2f * s2);
    }
}

// ================== bf16 HMMA masked attention =============================
// 256 threads, 8 warps; warp owns 16 i-rows x full F. m16n8k16: each 32-j
// tile needs 2 k-steps. W fragments generated in registers (bf16x2 packed
// j-pairs); B = H tile staged in smem pre-packed as bf16x2 j-pairs.
// Raw numerator (fp32 accum) + exact fp32 denominator partials out.
template <int F>
__global__ void __launch_bounds__(256, 2)
attn_hmma_kernel(const float* __restrict__ H, const float* __restrict__ T,
                 const float* __restrict__ R, const float* __restrict__ S2,
                 const float* __restrict__ E2p, const float* __restrict__ E2n,
                 const u32* __restrict__ mask,
                 float* __restrict__ Pn, float* __restrict__ Pd, int jsCount) {
    constexpr int SBU = F + 8;         // u32 row stride (8*tg+grp banks, distinct)
    constexpr int NT = F / 8;          // n-tiles per warp
    constexpr int NQ = 4 * F;          // staging uint4 quads per tile (16*(F/4))

    __shared__ u32  Bs[2][16 * SBU];   // [j-pair][f] bf16x2
    __shared__ float sSc[2][96];       // [s2 | e2p | e2n] x 32

    const int tid  = threadIdx.x;
    const int warp = tid >> 5;
    const int lane = tid & 31;
    const int grp  = lane >> 2;
    const int tg   = lane & 3;

    const int h   = blockIdx.y;
    const int js  = blockIdx.z;
    const int i0  = blockIdx.x * 128;
    const int jLen  = N_ / jsCount;
    const int jBase = js * jLen;
    const int nTiles = jLen / 32;

    const float* Hh  = H   + (size_t)h * N_ * F;
    const float* Th  = T   + (size_t)h * N_;
    const float* Rh  = R   + (size_t)h * N_;
    const float* S2h = S2  + (size_t)h * N_;
    const float* Pph = E2p + (size_t)h * N_;
    const float* Pnh = E2n + (size_t)h * N_;

    const int rowA = i0 + warp * 16 + grp;
    const int rowB = rowA + 8;
    const float T0 = Th[rowA], R0 = Rh[rowA];
    const float T1 = Th[rowB], R1 = Rh[rowB];

    float acc[NT][4];
#pragma unroll
    for (int nt = 0; nt < NT; nt++)
#pragma unroll
        for (int q = 0; q < 4; q++) acc[nt][q] = 0.f;
    float ds0 = 0.f, ds1 = 0.f;

    // staging coords: quad index -> (j-pair, f-quad)
    const int sjp = tid / (F / 4);
    const int sfq = tid % (F / 4);
    const bool doStage = (tid < NQ);
    const float* hs0 = Hh + (size_t)(jBase + 2 * sjp) * F + 4 * sfq;
    const float* hs1 = hs0 + F;

    for (int t = 0; t < nTiles; t++) {
        const int buf = t & 1;
        const int jA  = jBase + t * 32;

        // mask words (issued before the barrier; L2 latency hides under sync)
        const u32 mw0 = __ldg(mask + (size_t)rowA * MW_ + (jA >> 5));
        const u32 mw1 = __ldg(mask + (size_t)rowB * MW_ + (jA >> 5));

        // ---- stage B tile: Bs[jp][f] = bf16x2(H[jA+2jp][f], H[jA+2jp+1][f]) ----
        if (doStage) {
            float4 h0 = *reinterpret_cast<const float4*>(hs0 + (size_t)t * 32 * F);
            float4 h1 = *reinterpret_cast<const float4*>(hs1 + (size_t)t * 32 * F);
            uint4 tv;
            tv.x = packbf(h1.x, h0.x);
            tv.y = packbf(h1.y, h0.y);
            tv.z = packbf(h1.z, h0.z);
            tv.w = packbf(h1.w, h0.w);
            *reinterpret_cast<uint4*>(&Bs[buf][sjp * SBU + 4 * sfq]) = tv;
        }
        // ---- stage score arrays ----
        if (tid < 96) {
            const float* src = (tid < 32) ? S2h : (tid < 64) ? Pph : Pnh;
            sSc[buf][tid] = src[jA + (tid & 31)];
        }
        __syncthreads();

        const float* s2p = sSc[buf];
        const float* ppp = sSc[buf] + 32;
        const float* npp = sSc[buf] + 64;

#pragma unroll
        for (int kk = 0; kk < 2; kk++) {
            const int cL = 16 * kk + 2 * tg;      // low j pair
            const int cH = cL + 8;                // high j pair
            const float2 s2a = *reinterpret_cast<const float2*>(s2p + cL);
            const float2 s2b = *reinterpret_cast<const float2*>(s2p + cH);
            const float2 pa  = *reinterpret_cast<const float2*>(ppp + cL);
            const float2 pb  = *reinterpret_cast<const float2*>(ppp + cH);
            const float2 na  = *reinterpret_cast<const float2*>(npp + cL);
            const float2 nb  = *reinterpret_cast<const float2*>(npp + cH);
            // 8 w values: rows {A,B} x j {cL, cL+1, cH, cH+1}
            float wA0 = ((mw0 >> cL) & 1u)       ? ((s2a.x >= T0) ? pa.x * R0 : na.x) : 0.f;
            float wA1 = ((mw0 >> (cL + 1)) & 1u) ? ((s2a.y >= T0) ? pa.y * R0 : na.y) : 0.f;
            float wA2 = ((mw0 >> cH) & 1u)       ? ((s2b.x >= T0) ? pb.x * R0 : nb.x) : 0.f;
            float wA3 = ((mw0 >> (cH + 1)) & 1u) ? ((s2b.y >= T0) ? pb.y * R0 : nb.y) : 0.f;
            float wB0 = ((mw1 >> cL) & 1u)       ? ((s2a.x >= T1) ? pa.x * R1 : na.x) : 0.f;
            float wB1 = ((mw1 >> (cL + 1)) & 1u) ? ((s2a.y >= T1) ? pa.y * R1 : na.y) : 0.f;
            float wB2 = ((mw1 >> cH) & 1u)       ? ((s2b.x >= T1) ? pb.x * R1 : nb.x) : 0.f;
            float wB3 = ((mw1 >> (cH + 1)) & 1u) ? ((s2b.y >= T1) ? pb.y * R1 : nb.y) : 0.f;
            ds0 += (wA0 + wA1) + (wA2 + wA3);
            ds1 += (wB0 + wB1) + (wB2 + wB3);
            const u32 a0 = packbf(wA1, wA0);      // row A, k = 2tg, 2tg+1
            const u32 a1 = packbf(wB1, wB0);      // row B (grp+8)
            const u32 a2 = packbf(wA3, wA2);      // row A, k = 2tg+8, 2tg+9
            const u32 a3 = packbf(wB3, wB2);
            const u32* b0p = &Bs[buf][(8 * kk + tg) * SBU + grp];
            const u32* b1p = &Bs[buf][(8 * kk + tg + 4) * SBU + grp];
#pragma unroll
            for (int nt = 0; nt < NT; nt++)
                mma_bf16(acc[nt], a0, a1, a2, a3, b0p[8 * nt], b1p[8 * nt]);
        }
    }

    // ---- denominator reduce across the 4 lanes of each row group ----
    ds0 += __shfl_xor_sync(0xffffffffu, ds0, 1);
    ds0 += __shfl_xor_sync(0xffffffffu, ds0, 2);
    ds1 += __shfl_xor_sync(0xffffffffu, ds1, 1);
    ds1 += __shfl_xor_sync(0xffffffffu, ds1, 2);

    // ---- store raw partials ----
    const size_t bidx = (size_t)(js * gridDim.y + h) * N_;
    float* dA = Pn + (bidx + rowA) * F;
    float* dB = Pn + (bidx + rowB) * F;
#pragma unroll
    for (int nt = 0; nt < NT; nt++) {
        *reinterpret_cast<float2*>(dA + nt * 8 + 2 * tg) =
            make_float2(acc[nt][0], acc[nt][1]);
        *reinterpret_cast<float2*>(dB + nt * 8 + 2 * tg) =
            make_float2(acc[nt][2], acc[nt][3]);
    }
    if (tg == 0) {
        Pd[bidx + rowA] = ds0;
        Pd[bidx + rowB] = ds1;
    }
}

// ---------------- layer-1 combine: x2 = mean_h elu(sum Pn / sum Pd) --------
__global__ void combine1_kernel(const float* __restrict__ Pn,
                                const float* __restrict__ Pd,
                                float* __restrict__ x2) {
    int idx = blockIdx.x * blockDim.x + threadIdx.x;
    int i = idx >> 6, f = idx & 63;
    float s = 0.f;
#pragma unroll
    for (int h = 0; h < NH_; h++) {
        float num = 0.f, den = 0.f;
#pragma unroll
        for (int js = 0; js < JS1_; js++) {
            size_t b = ((size_t)(js * NH_ + h)) * N_ + i;
            num += Pn[b * F1_ + f];
            den += Pd[b];
        }
        float v = num / den;
        s += (v > 0.f) ? v : (expf(v) - 1.f);
    }
    x2[idx] = 0.25f * s;
}

// ---------------- layer-2 finalize: out = elu(sum Pn / sum Pd) -------------
__global__ void finalize2_kernel(const float* __restrict__ Pn,
                                 const float* __restrict__ Pd,
                                 float* __restrict__ out) {
    int idx = blockIdx.x * blockDim.x + threadIdx.x;
    int i = idx >> 5, f = idx & 31;
    float num = 0.f, den = 0.f;
#pragma unroll
    for (int js = 0; js < JS2_; js++) {
        size_t b = (size_t)js * N_ + i;
        num += Pn[b * F2_ + f];
        den += Pd[b];
    }
    float v = num / den;
    out[idx] = (v > 0.f) ? v : (expf(v) - 1.f);
}

// ---------------------------------------------------------------------------
extern "C" void kernel_launch(void* const* d_in, const int* /*in_sizes*/, int /*n_in*/,
                              void* d_out, int /*out_size*/) {
    const float* x   = (const float*)d_in[0];
    const int*   adj = (const int*)d_in[1];
    const float* Wh  = (const float*)d_in[2];
    const float* ah  = (const float*)d_in[3];
    const float* Wo  = (const float*)d_in[4];
    const float* ao  = (const float*)d_in[5];
    float*       out = (float*)d_out;

    void* sp = nullptr;
    cudaGetSymbolAddress(&sp, g_s);
    Scratch* s = (Scratch*)sp;

    // 1) adj -> bitmask (4.7 MB, L2-resident afterwards)
    pack_kernel<<<(unsigned)((size_t)N_ * N_ / 256), 256>>>(adj, s->mask);
    // 2) layer-1 head transforms: H1[h] = x @ W_heads[h]
    gemm_kernel<F1_><<<dim3(N_ / 128, NH_), 256>>>(x, Wh, s->H1, 256);
    // 3) per-node scores & exponentials
    scores_kernel<F1_><<<(NH_ * N_) / 8, 256>>>(s->H1, ah, s->T1, s->R1, s->S21,
                                                s->E2p1, s->E2n1, NH_);
    // 4) bf16 HMMA masked attention, 4 heads, 3-way j-split -> raw partials
    attn_hmma_kernel<F1_><<<dim3(N_ / 128, NH_, JS1_), 256>>>(
        s->H1, s->T1, s->R1, s->S21, s->E2p1, s->E2n1, s->mask, s->P1n, s->P1d, JS1_);
    // 5) x2 = mean_h elu(num/den)
    combine1_kernel<<<(N_ * F1_) / 256, 256>>>(s->P1n, s->P1d, s->x2);
    // 6) layer-2 transform: H2 = x2 @ W_out
    gemm_kernel<F2_><<<dim3(N_ / 256, 1), 256>>>(s->x2, Wo, s->H2, 64);
    // 7) layer-2 scores
    scores_kernel<F2_><<<N_ / 8, 256>>>(s->H2, ao, s->T2, s->R2, s->S22,
                                        s->E2p2, s->E2n2, 1);
    // 8) layer-2 attention, 12-way j-split -> raw partials
    attn_hmma_kernel<F2_><<<dim3(N_ / 128, 1, JS2_), 256>>>(
        s->H2, s->T2, s->R2, s->S22, s->E2p2, s->E2n2, s->mask, s->P2n, s->P2d, JS2_);
    // 9) final divide + elu straight into d_out
    finalize2_kernel<<<(N_ * F2_) / 256, 256>>>(s->P2n, s->P2d, out);
}

// round 16
// speedup vs baseline: 1.2083x; 1.2083x over previous
#include <cuda_runtime.h>
#include <cuda_fp16.h>
#include <cstdint>
#include <cstddef>

// ---------------------------------------------------------------------------
// GAT, N=6144, F_in=256, F_hid=64, F_out=32, H=4, dense adj.
// attn_ij = w_ij / sum_j w_ij. With per-row rescale by e^{-0.8 s1_i} (cancels
// in the ratio):  w_ij = mask_ij * ( s2_j >= -s1_i ? e^{s2_j}
//                                                  : e^{0.2 s2_j} * e^{-0.8 s1_i} )
// -> all w values are O(1..300): safe for fp16. fp16 mantissa == tf32 mantissa.
// Masked attention via fp16 HMMA m16n8k16 (R13 shape: 256 thr, M_warp=16).
// L1-wavefront diet: transposed mask staged via smem, fp16 H staging (PRMT
// j-pair pack), scores as float4 per j staged via smem. Exact fp32 denominator.
// ---------------------------------------------------------------------------

typedef uint32_t u32;

constexpr int N_  = 6144;
constexpr int NH_ = 4;
constexpr int F1_ = 64;
constexpr int F2_ = 32;
constexpr int MW_ = N_ / 32;   // 192 mask words per row
constexpr int JS1_ = 3;        // j-splits, layer 1 -> 576 CTAs
constexpr int JS2_ = 12;       // j-splits, layer 2 -> 576 CTAs

struct Scratch {
    u32 maskT[(size_t)MW_ * N_];              // [jw][i] transposed
    float  H1[(size_t)NH_ * N_ * F1_];
    __half H1h[(size_t)NH_ * N_ * F1_];
    float P1n[(size_t)JS1_ * NH_ * N_ * F1_];
    float P1d[(size_t)JS1_ * NH_ * N_];
    float x2[(size_t)N_ * F1_];
    float  H2[(size_t)N_ * F2_];
    __half H2h[(size_t)N_ * F2_];
    float P2n[(size_t)JS2_ * N_ * F2_];
    float P2d[(size_t)JS2_ * N_];
    float T1[NH_ * N_], R1[NH_ * N_];
    float T2[N_], R2[N_];
    float4 SC1[NH_ * N_];                     // (s2, e^{s2}, e^{0.2 s2}, 0)
    float4 SC2[N_];
};
__device__ Scratch g_s;

// ---------------- helpers ---------------------------------------------------
__device__ __forceinline__ u32 packh(float hi, float lo) {
    u32 r;
    asm("cvt.rn.f16x2.f32 %0, %1, %2;" : "=r"(r) : "f"(hi), "f"(lo));
    return r;
}
__device__ __forceinline__ void mma_f16(float* c,
                                        u32 a0, u32 a1, u32 a2, u32 a3,
                                        u32 b0, u32 b1) {
    asm volatile(
        "mma.sync.aligned.m16n8k16.row.col.f32.f16.f16.f32 "
        "{%0,%1,%2,%3}, {%4,%5,%6,%7}, {%8,%9}, {%0,%1,%2,%3};"
        : "+f"(c[0]), "+f"(c[1]), "+f"(c[2]), "+f"(c[3])
        : "r"(a0), "r"(a1), "r"(a2), "r"(a3), "r"(b0), "r"(b1));
}

// ---------------- adj -> transposed bitmask: maskT[jw][i] ------------------
__global__ void pack_kernel(const int* __restrict__ adj, u32* __restrict__ mt) {
    size_t gid = (size_t)blockIdx.x * blockDim.x + threadIdx.x;  // i*N + j
    int v = adj[gid] > 0;
    u32 m = __ballot_sync(0xffffffffu, v);
    if ((threadIdx.x & 31) == 0) {
        size_t w = gid >> 5;
        int i  = (int)(w / MW_);
        int jw = (int)(w % MW_);
        mt[(size_t)jw * N_ + i] = m;
    }
}

// ---------------- small fp32 GEMM: C[h] = A @ B[h] (+ fp16 copy) -----------
template <int F>
__global__ void gemm_kernel(const float* __restrict__ A, const float* __restrict__ B,
                            float* __restrict__ C, __half* __restrict__ C2, int K) {
    constexpr int TX = F / 4;
    constexpr int TY = 256 / TX;
    constexpr int RM = TY * 8;
    constexpr int TK = 16;
    __shared__ float xs[RM][TK + 1];
    __shared__ float ws[TK][F + 4];
    const int h  = blockIdx.y;
    const int i0 = blockIdx.x * RM;
    const float* Bh = B + (size_t)h * K * F;
    float*       Ch = C + (size_t)h * N_ * F;
    __half*      C2h = C2 + (size_t)h * N_ * F;
    const int tid = threadIdx.x;
    const int tx = tid % TX, ty = tid / TX;
    float acc[8][4] = {};
    for (int k0 = 0; k0 < K; k0 += TK) {
        for (int idx = tid; idx < RM * TK; idx += 256) {
            int r = idx / TK, c = idx % TK;
            xs[r][c] = A[(size_t)(i0 + r) * K + k0 + c];
        }
        for (int idx = tid; idx < TK * F; idx += 256) {
            int r = idx / F, c = idx % F;
            ws[r][c] = Bh[(size_t)(k0 + r) * F + c];
        }
        __syncthreads();
#pragma unroll
        for (int kk = 0; kk < TK; kk++) {
            float a[8], b[4];
#pragma unroll
            for (int r = 0; r < 8; r++) a[r] = xs[ty * 8 + r][kk];
#pragma unroll
            for (int c = 0; c < 4; c++) b[c] = ws[kk][tx * 4 + c];
#pragma unroll
            for (int r = 0; r < 8; r++)
#pragma unroll
                for (int c = 0; c < 4; c++)
                    acc[r][c] = fmaf(a[r], b[c], acc[r][c]);
        }
        __syncthreads();
    }
#pragma unroll
    for (int r = 0; r < 8; r++)
#pragma unroll
        for (int c = 0; c < 4; c++) {
            size_t o = (size_t)(i0 + ty * 8 + r) * F + tx * 4 + c;
            Ch[o]  = acc[r][c];
            C2h[o] = __float2half(acc[r][c]);
        }
}

// ---------------- per-node scores: T=-s1, R=e^{-0.8 s1}, SC=(s2,e^{s2},e^{.2 s2}) --
template <int F>
__global__ void scores_kernel(const float* __restrict__ H, const float* __restrict__ a,
                              float* __restrict__ T, float* __restrict__ R,
                              float4* __restrict__ SC, int NH) {
    int gw   = (int)((blockIdx.x * blockDim.x + threadIdx.x) >> 5);
    int lane = threadIdx.x & 31;
    if (gw >= NH * N_) return;
    int h = gw / N_, i = gw % N_;
    const float* Hi = H + ((size_t)h * N_ + i) * F;
    const float* a1 = a + (size_t)h * 2 * F;
    const float* a2 = a1 + F;
    float s1 = 0.f, s2 = 0.f;
    for (int f = lane; f < F; f += 32) {
        float hv = Hi[f];
        s1 = fmaf(hv, a1[f], s1);
        s2 = fmaf(hv, a2[f], s2);
    }
#pragma unroll
    for (int o = 16; o; o >>= 1) {
        s1 += __shfl_xor_sync(0xffffffffu, s1, o);
        s2 += __shfl_xor_sync(0xffffffffu, s2, o);
    }
    if (lane == 0) {
        int idx = h * N_ + i;
        T[idx] = -s1;
        R[idx] = expf(-0.8f * s1);
        SC[idx] = make_float4(s2, expf(s2), expf(0.2f * s2), 0.f);
    }
}

// ================== fp16 HMMA masked attention =============================
// 256 threads, 8 warps; warp owns 16 i-rows x full F. m16n8k16, 2 k-steps
// per 32-j tile. W fragments generated in registers from staged scores +
// staged transposed mask; B = fp16 H tile staged as j-pair f16x2.
template <int F>
__global__ void __launch_bounds__(256, 2)
attn_hmma_kernel(const __half* __restrict__ Hh2, const float* __restrict__ T,
                 const float* __restrict__ R, const float4* __restrict__ SC,
                 const u32* __restrict__ maskT,
                 float* __restrict__ Pn, float* __restrict__ Pd, int jsCount) {
    constexpr int SBU = F + 8;         // u32 row stride per j-pair
    constexpr int NT  = F / 8;         // n-tiles per warp
    constexpr int NST = 4 * F;         // staging threads (16 jpairs * F/4)

    __shared__ u32    Bs[2][16 * SBU]; // [j-pair][f] f16x2 (lo=j0, hi=j1)
    __shared__ float4 sSC[2][32];
    __shared__ u32    sMk[2][128];

    const int tid  = threadIdx.x;
    const int warp = tid >> 5;
    const int lane = tid & 31;
    const int grp  = lane >> 2;
    const int tg   = lane & 3;

    const int h   = blockIdx.y;
    const int js  = blockIdx.z;
    const int i0  = blockIdx.x * 128;
    const int jLen  = N_ / jsCount;
    const int jBase = js * jLen;
    const int nTiles = jLen / 32;

    const __half*  Hh  = Hh2 + (size_t)h * N_ * F;
    const float*   Th  = T   + (size_t)h * N_;
    const float*   Rh  = R   + (size_t)h * N_;
    const float4*  SCh = SC  + (size_t)h * N_;

    const int rowA = i0 + warp * 16 + grp;
    const int rowB = rowA + 8;
    const float T0 = Th[rowA], R0 = Rh[rowA];
    const float T1 = Th[rowB], R1 = Rh[rowB];

    float acc[NT][4];
#pragma unroll
    for (int nt = 0; nt < NT; nt++)
#pragma unroll
        for (int q = 0; q < 4; q++) acc[nt][q] = 0.f;
    float ds0 = 0.f, ds1 = 0.f;

    // staging coords
    const int sjp = tid / (F / 4);
    const int sfq = tid % (F / 4);
    const bool doStage = (tid < NST);
    const __half* hsA = Hh + (size_t)(jBase + 2 * sjp) * F + 4 * sfq;

    for (int t = 0; t < nTiles; t++) {
        const int buf = t & 1;
        const int jA  = jBase + t * 32;

        // ---- stage B tile (fp16 pairs via PRMT) ----
        if (doStage) {
            uint2 u = *reinterpret_cast<const uint2*>(hsA + (size_t)t * 32 * F);
            uint2 v = *reinterpret_cast<const uint2*>(hsA + (size_t)t * 32 * F + F);
            uint4 tv;
            tv.x = __byte_perm(u.x, v.x, 0x5410);   // f+0: lo=j0, hi=j1
            tv.y = __byte_perm(u.x, v.x, 0x7632);   // f+1
            tv.z = __byte_perm(u.y, v.y, 0x5410);   // f+2
            tv.w = __byte_perm(u.y, v.y, 0x7632);   // f+3
            *reinterpret_cast<uint4*>(&Bs[buf][sjp * SBU + 4 * sfq]) = tv;
        }
        // ---- stage scores (float4/j) and transposed mask words ----
        if (tid < 32)
            sSC[buf][tid] = SCh[jA + tid];
        if (tid >= 128 && tid < 256)
            sMk[buf][tid - 128] = maskT[(size_t)(jA >> 5) * N_ + i0 + (tid - 128)];
        __syncthreads();

        const u32 mw0 = sMk[buf][warp * 16 + grp];
        const u32 mw1 = sMk[buf][warp * 16 + grp + 8];

#pragma unroll
        for (int kk = 0; kk < 2; kk++) {
            const int cL = 16 * kk + 2 * tg;
            const int cH = cL + 8;
            const float4 sa0 = sSC[buf][cL],     sa1 = sSC[buf][cL + 1];
            const float4 sb0 = sSC[buf][cH],     sb1 = sSC[buf][cH + 1];
            // w = mask ? (s2 >= T ? e^{s2} : e^{0.2 s2} * R_i) : 0
            float wA0 = ((mw0 >> cL) & 1u)       ? ((sa0.x >= T0) ? sa0.y : sa0.z * R0) : 0.f;
            float wA1 = ((mw0 >> (cL + 1)) & 1u) ? ((sa1.x >= T0) ? sa1.y : sa1.z * R0) : 0.f;
            float wA2 = ((mw0 >> cH) & 1u)       ? ((sb0.x >= T0) ? sb0.y : sb0.z * R0) : 0.f;
            float wA3 = ((mw0 >> (cH + 1)) & 1u) ? ((sb1.x >= T0) ? sb1.y : sb1.z * R0) : 0.f;
            float wB0 = ((mw1 >> cL) & 1u)       ? ((sa0.x >= T1) ? sa0.y : sa0.z * R1) : 0.f;
            float wB1 = ((mw1 >> (cL + 1)) & 1u) ? ((sa1.x >= T1) ? sa1.y : sa1.z * R1) : 0.f;
            float wB2 = ((mw1 >> cH) & 1u)       ? ((sb0.x >= T1) ? sb0.y : sb0.z * R1) : 0.f;
            float wB3 = ((mw1 >> (cH + 1)) & 1u) ? ((sb1.x >= T1) ? sb1.y : sb1.z * R1) : 0.f;
            ds0 += (wA0 + wA1) + (wA2 + wA3);
            ds1 += (wB0 + wB1) + (wB2 + wB3);
            const u32 a0 = packh(wA1, wA0);     // lo = lower j (matches B pack)
            const u32 a1 = packh(wB1, wB0);
            const u32 a2 = packh(wA3, wA2);
            const u32 a3 = packh(wB3, wB2);
            const u32* b0p = &Bs[buf][(8 * kk + tg) * SBU + grp];
            const u32* b1p = &Bs[buf][(8 * kk + tg + 4) * SBU + grp];
#pragma unroll
            for (int nt = 0; nt < NT; nt++)
                mma_f16(acc[nt], a0, a1, a2, a3, b0p[8 * nt], b1p[8 * nt]);
        }
    }

    // ---- denominator reduce across the 4 lanes of each row group ----
    ds0 += __shfl_xor_sync(0xffffffffu, ds0, 1);
    ds0 += __shfl_xor_sync(0xffffffffu, ds0, 2);
    ds1 += __shfl_xor_sync(0xffffffffu, ds1, 1);
    ds1 += __shfl_xor_sync(0xffffffffu, ds1, 2);

    // ---- store raw partials ----
    const size_t bidx = (size_t)(js * gridDim.y + h) * N_;
    float* dA = Pn + (bidx + rowA) * F;
    float* dB = Pn + (bidx + rowB) * F;
#pragma unroll
    for (int nt = 0; nt < NT; nt++) {
        *reinterpret_cast<float2*>(dA + nt * 8 + 2 * tg) =
            make_float2(acc[nt][0], acc[nt][1]);
        *reinterpret_cast<float2*>(dB + nt * 8 + 2 * tg) =
            make_float2(acc[nt][2], acc[nt][3]);
    }
    if (tg == 0) {
        Pd[bidx + rowA] = ds0;
        Pd[bidx + rowB] = ds1;
    }
}

// ---------------- layer-1 combine: x2 = mean_h elu(sum Pn / sum Pd) --------
__global__ void combine1_kernel(const float* __restrict__ Pn,
                                const float* __restrict__ Pd,
                                float* __restrict__ x2) {
    int idx = blockIdx.x * blockDim.x + threadIdx.x;
    int i = idx >> 6, f = idx & 63;
    float s = 0.f;
#pragma unroll
    for (int h = 0; h < NH_; h++) {
        float num = 0.f, den = 0.f;
#pragma unroll
        for (int js = 0; js < JS1_; js++) {
            size_t b = ((size_t)(js * NH_ + h)) * N_ + i;
            num += Pn[b * F1_ + f];
            den += Pd[b];
        }
        float v = num / den;
        s += (v > 0.f) ? v : (expf(v) - 1.f);
    }
    x2[idx] = 0.25f * s;
}

// ---------------- layer-2 finalize: out = elu(sum Pn / sum Pd) -------------
__global__ void finalize2_kernel(const float* __restrict__ Pn,
                                 const float* __restrict__ Pd,
                                 float* __restrict__ out) {
    int idx = blockIdx.x * blockDim.x + threadIdx.x;
    int i = idx >> 5, f = idx & 31;
    float num = 0.f, den = 0.f;
#pragma unroll
    for (int js = 0; js < JS2_; js++) {
        size_t b = (size_t)js * N_ + i;
        num += Pn[b * F2_ + f];
        den += Pd[b];
    }
    float v = num / den;
    out[idx] = (v > 0.f) ? v : (expf(v) - 1.f);
}

// ---------------------------------------------------------------------------
extern "C" void kernel_launch(void* const* d_in, const int* /*in_sizes*/, int /*n_in*/,
                              void* d_out, int /*out_size*/) {
    const float* x   = (const float*)d_in[0];
    const int*   adj = (const int*)d_in[1];
    const float* Wh  = (const float*)d_in[2];
    const float* ah  = (const float*)d_in[3];
    const float* Wo  = (const float*)d_in[4];
    const float* ao  = (const float*)d_in[5];
    float*       out = (float*)d_out;

    void* sp = nullptr;
    cudaGetSymbolAddress(&sp, g_s);
    Scratch* s = (Scratch*)sp;

    // 1) adj -> transposed bitmask (L2-resident afterwards)
    pack_kernel<<<(unsigned)((size_t)N_ * N_ / 256), 256>>>(adj, s->maskT);
    // 2) layer-1 head transforms: H1[h] = x @ W_heads[h] (fp32 + fp16 copies)
    gemm_kernel<F1_><<<dim3(N_ / 128, NH_), 256>>>(x, Wh, s->H1, s->H1h, 256);
    // 3) per-node scores (rescaled form)
    scores_kernel<F1_><<<(NH_ * N_) / 8, 256>>>(s->H1, ah, s->T1, s->R1, s->SC1, NH_);
    // 4) fp16 HMMA masked attention, 4 heads, 3-way j-split -> raw partials
    attn_hmma_kernel<F1_><<<dim3(N_ / 128, NH_, JS1_), 256>>>(
        s->H1h, s->T1, s->R1, s->SC1, s->maskT, s->P1n, s->P1d, JS1_);
    // 5) x2 = mean_h elu(num/den)
    combine1_kernel<<<(N_ * F1_) / 256, 256>>>(s->P1n, s->P1d, s->x2);
    // 6) layer-2 transform: H2 = x2 @ W_out
    gemm_kernel<F2_><<<dim3(N_ / 256, 1), 256>>>(s->x2, Wo, s->H2, s->H2h, 64);
    // 7) layer-2 scores
    scores_kernel<F2_><<<N_ / 8, 256>>>(s->H2, ao, s->T2, s->R2, s->SC2, 1);
    // 8) layer-2 attention, 12-way j-split -> raw partials
    attn_hmma_kernel<F2_><<<dim3(N_ / 128, 1, JS2_), 256>>>(
        s->H2h, s->T2, s->R2, s->SC2, s->maskT, s->P2n, s->P2d, JS2_);
    // 9) final divide + elu straight into d_out
    finalize2_kernel<<<(N_ * F2_) / 256, 256>>>(s->P2n, s->P2d, out);
}